// round 1
// baseline (speedup 1.0000x reference)
#include <cuda_runtime.h>
#include <math.h>

// Problem shape (fixed by the dataset): z [8192,256] f32, embedding [4096,256] f32.
// Output: adj = sigmoid(z z^T) [8192*8192] f32, then argmax indices [8192] as f32.

#define KDIM 256
#define TILE 128
#define KB   16
#define NMAX 8192
#define VMAX 4096
#define NSPLIT 8          // column splits for the cosine kernel (occupancy)

// Scratch (device globals: no allocation allowed in kernel_launch)
__device__ float g_zn[NMAX * KDIM];       // normalized z
__device__ float g_en[VMAX * KDIM];       // normalized embedding
__device__ float g_bestval[NMAX * NSPLIT];
__device__ int   g_bestidx[NMAX * NSPLIT];

// ---------------------------------------------------------------------------
// Normalize rows of z and embedding (eps-clamped L2 norm, matching reference)
// grid = N + V blocks, 256 threads (one per K element)
// ---------------------------------------------------------------------------
__global__ void normalize_kernel(const float* __restrict__ z,
                                 const float* __restrict__ e,
                                 int N, int V) {
    int row = blockIdx.x;
    const float* src;
    float* dst;
    if (row < N) { src = z + (size_t)row * KDIM; dst = g_zn + (size_t)row * KDIM; }
    else         { src = e + (size_t)(row - N) * KDIM; dst = g_en + (size_t)(row - N) * KDIM; }

    int tid = threadIdx.x;
    float v = src[tid];
    float ss = v * v;
    #pragma unroll
    for (int o = 16; o; o >>= 1) ss += __shfl_xor_sync(0xffffffffu, ss, o);

    __shared__ float s_partial[8];
    __shared__ float s_total;
    if ((tid & 31) == 0) s_partial[tid >> 5] = ss;
    __syncthreads();
    if (tid == 0) {
        float t = 0.f;
        #pragma unroll
        for (int i = 0; i < 8; i++) t += s_partial[i];
        s_total = t;
    }
    __syncthreads();
    float nrm = sqrtf(s_total);
    float inv = 1.0f / fmaxf(nrm, 1e-8f);
    dst[tid] = v * inv;
}

// ---------------------------------------------------------------------------
// Shared 128x128 f32 GEMM tile body (K=256, KB=16 chunks), 256 threads,
// 8x8 register microtile per thread. A, B are row-major [*, 256].
// ---------------------------------------------------------------------------
__device__ __forceinline__ void gemm_tile_128(const float* __restrict__ A,
                                              const float* __restrict__ B,
                                              float (&acc)[8][8],
                                              float (*As)[TILE],
                                              float (*Bs)[TILE],
                                              int tid, int rowBase, int colBase) {
    for (int kc = 0; kc < KDIM; kc += KB) {
        // Cooperative load: 128 rows x 16 k values for both tiles.
        int lr = tid >> 2;          // 0..63
        int lc = (tid & 3) << 2;    // 0,4,8,12
        #pragma unroll
        for (int h = 0; h < 2; h++) {
            int r = lr + 64 * h;
            float4 va = *(const float4*)(A + (size_t)r * KDIM + kc + lc);
            As[lc + 0][r] = va.x; As[lc + 1][r] = va.y;
            As[lc + 2][r] = va.z; As[lc + 3][r] = va.w;
            float4 vb = *(const float4*)(B + (size_t)r * KDIM + kc + lc);
            Bs[lc + 0][r] = vb.x; Bs[lc + 1][r] = vb.y;
            Bs[lc + 2][r] = vb.z; Bs[lc + 3][r] = vb.w;
        }
        __syncthreads();

        #pragma unroll
        for (int k = 0; k < KB; k++) {
            float a[8], b[8];
            float4 a0 = *(const float4*)&As[k][rowBase];
            float4 a1 = *(const float4*)&As[k][rowBase + 4];
            float4 b0 = *(const float4*)&Bs[k][colBase];
            float4 b1 = *(const float4*)&Bs[k][colBase + 4];
            a[0]=a0.x; a[1]=a0.y; a[2]=a0.z; a[3]=a0.w;
            a[4]=a1.x; a[5]=a1.y; a[6]=a1.z; a[7]=a1.w;
            b[0]=b0.x; b[1]=b0.y; b[2]=b0.z; b[3]=b0.w;
            b[4]=b1.x; b[5]=b1.y; b[6]=b1.z; b[7]=b1.w;
            #pragma unroll
            for (int i = 0; i < 8; i++)
                #pragma unroll
                for (int j = 0; j < 8; j++)
                    acc[i][j] = fmaf(a[i], b[j], acc[i][j]);
        }
        __syncthreads();
    }
}

// ---------------------------------------------------------------------------
// adj = sigmoid(z z^T): grid (N/128, N/128), 256 threads
// ---------------------------------------------------------------------------
__global__ void __launch_bounds__(256, 2) adj_kernel(const float* __restrict__ z,
                                                     float* __restrict__ out,
                                                     int N) {
    __shared__ float As[KB][TILE];
    __shared__ float Bs[KB][TILE];

    int tid = threadIdx.x;
    int rowBase = (tid >> 4) << 3;
    int colBase = (tid & 15) << 3;
    int bi = blockIdx.y, bj = blockIdx.x;

    const float* A = z + (size_t)bi * TILE * KDIM;
    const float* B = z + (size_t)bj * TILE * KDIM;

    float acc[8][8];
    #pragma unroll
    for (int i = 0; i < 8; i++)
        #pragma unroll
        for (int j = 0; j < 8; j++) acc[i][j] = 0.f;

    gemm_tile_128(A, B, acc, As, Bs, tid, rowBase, colBase);

    #pragma unroll
    for (int i = 0; i < 8; i++) {
        size_t row = (size_t)bi * TILE + rowBase + i;
        size_t base = row * (size_t)N + (size_t)bj * TILE + colBase;
        #pragma unroll
        for (int jj = 0; jj < 2; jj++) {
            float4 r;
            r.x = 1.0f / (1.0f + expf(-acc[i][jj * 4 + 0]));
            r.y = 1.0f / (1.0f + expf(-acc[i][jj * 4 + 1]));
            r.z = 1.0f / (1.0f + expf(-acc[i][jj * 4 + 2]));
            r.w = 1.0f / (1.0f + expf(-acc[i][jj * 4 + 3]));
            *(float4*)(out + base + jj * 4) = r;
        }
    }
}

// ---------------------------------------------------------------------------
// Cosine similarity + running argmax. grid (NSPLIT, N/128), 256 threads.
// Each block: 128 z-rows x (V/NSPLIT) codebook columns, in 128-col tiles.
// ---------------------------------------------------------------------------
__global__ void __launch_bounds__(256, 2) cos_kernel(int N, int V) {
    __shared__ float As[KB][TILE];
    __shared__ float Bs[KB][TILE];

    int tid = threadIdx.x;
    int rowBase = (tid >> 4) << 3;
    int colBase = (tid & 15) << 3;
    int bi = blockIdx.y;
    int split = blockIdx.x;
    int colsPerSplit = V / NSPLIT;          // 512
    int tilesPerSplit = colsPerSplit / TILE; // 4

    const float* A = g_zn + (size_t)bi * TILE * KDIM;

    float bestv[8];
    int   besti[8];
    #pragma unroll
    for (int i = 0; i < 8; i++) { bestv[i] = -2.0f; besti[i] = 0; }

    for (int ct = 0; ct < tilesPerSplit; ct++) {
        int cbase = split * colsPerSplit + ct * TILE;
        const float* B = g_en + (size_t)cbase * KDIM;

        float acc[8][8];
        #pragma unroll
        for (int i = 0; i < 8; i++)
            #pragma unroll
            for (int j = 0; j < 8; j++) acc[i][j] = 0.f;

        gemm_tile_128(A, B, acc, As, Bs, tid, rowBase, colBase);

        // Running argmax. Column indices ascend across iterations, so a
        // strict > preserves the first (smallest-index) maximum.
        #pragma unroll
        for (int i = 0; i < 8; i++) {
            #pragma unroll
            for (int j = 0; j < 8; j++) {
                int idx = cbase + colBase + j;
                if (acc[i][j] > bestv[i]) { bestv[i] = acc[i][j]; besti[i] = idx; }
            }
        }
    }

    // Reduce across the 16 lanes that share each row group (width-16 shuffle).
    #pragma unroll
    for (int i = 0; i < 8; i++) {
        float v = bestv[i];
        int   id = besti[i];
        #pragma unroll
        for (int off = 8; off; off >>= 1) {
            float v2 = __shfl_down_sync(0xffffffffu, v, off, 16);
            int   i2 = __shfl_down_sync(0xffffffffu, id, off, 16);
            if (v2 > v || (v2 == v && i2 < id)) { v = v2; id = i2; }
        }
        if ((tid & 15) == 0) {
            int row = bi * TILE + rowBase + i;
            g_bestval[row * NSPLIT + split] = v;
            g_bestidx[row * NSPLIT + split] = id;
        }
    }
}

// ---------------------------------------------------------------------------
// Final merge over NSPLIT partial argmaxes; write indices (as float) after adj.
// ---------------------------------------------------------------------------
__global__ void argmax_final_kernel(float* __restrict__ out, int N) {
    int row = blockIdx.x * blockDim.x + threadIdx.x;
    if (row >= N) return;
    float bv = -3.0f;
    int bi = 0;
    // Splits are in ascending index order: strict > keeps the smallest index.
    #pragma unroll
    for (int s = 0; s < NSPLIT; s++) {
        float v = g_bestval[row * NSPLIT + s];
        int   id = g_bestidx[row * NSPLIT + s];
        if (v > bv) { bv = v; bi = id; }
    }
    out[(size_t)N * (size_t)N + row] = (float)bi;
}

// ---------------------------------------------------------------------------
extern "C" void kernel_launch(void* const* d_in, const int* in_sizes, int n_in,
                              void* d_out, int out_size) {
    const float* z = (const float*)d_in[0];
    const float* e = (const float*)d_in[1];
    float* out = (float*)d_out;

    int N = in_sizes[0] / KDIM;   // 8192
    int V = in_sizes[1] / KDIM;   // 4096

    normalize_kernel<<<N + V, 256>>>(z, e, N, V);

    dim3 gAdj(N / TILE, N / TILE);
    adj_kernel<<<gAdj, 256>>>(z, out, N);

    dim3 gCos(NSPLIT, N / TILE);
    cos_kernel<<<gCos, 256>>>(N, V);

    argmax_final_kernel<<<(N + 255) / 256, 256>>>(out, N);
}

// round 2
// speedup vs baseline: 1.2951x; 1.2951x over previous
#include <cuda_runtime.h>
#include <math.h>

// z [8192,256] f32, embedding [4096,256] f32.
// Output: adj = sigmoid(z z^T) [8192*8192] f32, then argmax indices [8192] as f32.
// adj is SYMMETRIC: compute only upper-triangular tiles, mirror-write the rest.

#define KDIM 256
#define TILE 128
#define KB   16
#define NMAX 8192
#define VMAX 4096
#define NSPLIT 8

__device__ float g_zn[NMAX * KDIM];
__device__ float g_en[VMAX * KDIM];
__device__ float g_bestval[NMAX * NSPLIT];
__device__ int   g_bestidx[NMAX * NSPLIT];

// ---------------------------------------------------------------------------
// Normalize rows (eps-clamped L2, matching reference)
// ---------------------------------------------------------------------------
__global__ void normalize_kernel(const float* __restrict__ z,
                                 const float* __restrict__ e,
                                 int N, int V) {
    int row = blockIdx.x;
    const float* src;
    float* dst;
    if (row < N) { src = z + (size_t)row * KDIM; dst = g_zn + (size_t)row * KDIM; }
    else         { src = e + (size_t)(row - N) * KDIM; dst = g_en + (size_t)(row - N) * KDIM; }

    int tid = threadIdx.x;
    float v = src[tid];
    float ss = v * v;
    #pragma unroll
    for (int o = 16; o; o >>= 1) ss += __shfl_xor_sync(0xffffffffu, ss, o);

    __shared__ float s_partial[8];
    __shared__ float s_total;
    if ((tid & 31) == 0) s_partial[tid >> 5] = ss;
    __syncthreads();
    if (tid == 0) {
        float t = 0.f;
        #pragma unroll
        for (int i = 0; i < 8; i++) t += s_partial[i];
        s_total = t;
    }
    __syncthreads();
    float nrm = sqrtf(s_total);
    float inv = 1.0f / fmaxf(nrm, 1e-8f);
    dst[tid] = v * inv;
}

// ---------------------------------------------------------------------------
// 128x128 f32 GEMM tile body (K=256), 256 threads, 8x8 microtile.
// ---------------------------------------------------------------------------
__device__ __forceinline__ void gemm_tile_128(const float* __restrict__ A,
                                              const float* __restrict__ B,
                                              float (&acc)[8][8],
                                              float (*As)[TILE],
                                              float (*Bs)[TILE],
                                              int tid, int rowBase, int colBase) {
    for (int kc = 0; kc < KDIM; kc += KB) {
        int lr = tid >> 2;
        int lc = (tid & 3) << 2;
        #pragma unroll
        for (int h = 0; h < 2; h++) {
            int r = lr + 64 * h;
            float4 va = *(const float4*)(A + (size_t)r * KDIM + kc + lc);
            As[lc + 0][r] = va.x; As[lc + 1][r] = va.y;
            As[lc + 2][r] = va.z; As[lc + 3][r] = va.w;
            float4 vb = *(const float4*)(B + (size_t)r * KDIM + kc + lc);
            Bs[lc + 0][r] = vb.x; Bs[lc + 1][r] = vb.y;
            Bs[lc + 2][r] = vb.z; Bs[lc + 3][r] = vb.w;
        }
        __syncthreads();

        #pragma unroll
        for (int k = 0; k < KB; k++) {
            float a[8], b[8];
            float4 a0 = *(const float4*)&As[k][rowBase];
            float4 a1 = *(const float4*)&As[k][rowBase + 4];
            float4 b0 = *(const float4*)&Bs[k][colBase];
            float4 b1 = *(const float4*)&Bs[k][colBase + 4];
            a[0]=a0.x; a[1]=a0.y; a[2]=a0.z; a[3]=a0.w;
            a[4]=a1.x; a[5]=a1.y; a[6]=a1.z; a[7]=a1.w;
            b[0]=b0.x; b[1]=b0.y; b[2]=b0.z; b[3]=b0.w;
            b[4]=b1.x; b[5]=b1.y; b[6]=b1.z; b[7]=b1.w;
            #pragma unroll
            for (int i = 0; i < 8; i++)
                #pragma unroll
                for (int j = 0; j < 8; j++)
                    acc[i][j] = fmaf(a[i], b[j], acc[i][j]);
        }
        __syncthreads();
    }
}

// ---------------------------------------------------------------------------
// adj: only upper-triangular tiles (bi <= bj). grid = 2080 linear blocks.
// Off-diagonal tiles also write their transpose via smem staging.
// ---------------------------------------------------------------------------
__global__ void __launch_bounds__(256, 2) adj_sym_kernel(const float* __restrict__ z,
                                                         float* __restrict__ out,
                                                         int N) {
    __shared__ float As[KB][TILE];
    __shared__ float Bs[KB][TILE];

    const int T = N / TILE;  // 64

    // Decode linear tile id -> (bi, bj), bi <= bj (row-major over upper tri).
    int t = blockIdx.x;
    int bi = 0;
    while (t >= (T - bi)) { t -= (T - bi); bi++; }
    int bj = bi + t;

    int tid = threadIdx.x;
    int rowBase = (tid >> 4) << 3;
    int colBase = (tid & 15) << 3;

    const float* A = z + (size_t)bi * TILE * KDIM;
    const float* B = z + (size_t)bj * TILE * KDIM;

    float acc[8][8];
    #pragma unroll
    for (int i = 0; i < 8; i++)
        #pragma unroll
        for (int j = 0; j < 8; j++) acc[i][j] = 0.f;

    gemm_tile_128(A, B, acc, As, Bs, tid, rowBase, colBase);

    // Sigmoid in place.
    #pragma unroll
    for (int i = 0; i < 8; i++)
        #pragma unroll
        for (int j = 0; j < 8; j++)
            acc[i][j] = __fdividef(1.0f, 1.0f + __expf(-acc[i][j]));

    // Normal (upper) tile write, coalesced.
    #pragma unroll
    for (int i = 0; i < 8; i++) {
        size_t row = (size_t)bi * TILE + rowBase + i;
        size_t base = row * (size_t)N + (size_t)bj * TILE + colBase;
        float4 r0 = make_float4(acc[i][0], acc[i][1], acc[i][2], acc[i][3]);
        float4 r1 = make_float4(acc[i][4], acc[i][5], acc[i][6], acc[i][7]);
        *(float4*)(out + base)     = r0;
        *(float4*)(out + base + 4) = r1;
    }

    if (bi == bj) return;

    // Mirror (lower) tile write: transpose through smem in 8 chunks of 16
    // mirror-rows, reusing As (16x128 floats = 8KB) as staging.
    float (*S)[TILE] = As;
    int myChunk = (tid & 15) >> 1;   // colBase / 16: which chunk this thread's cols fall in

    for (int c = 0; c < 8; c++) {
        __syncthreads();
        if (myChunk == c) {
            int jl = colBase - (c << 4);   // 0 or 8 within the chunk
            #pragma unroll
            for (int j = 0; j < 8; j++) {
                float4 v0 = make_float4(acc[0][j], acc[1][j], acc[2][j], acc[3][j]);
                float4 v1 = make_float4(acc[4][j], acc[5][j], acc[6][j], acc[7][j]);
                *(float4*)&S[jl + j][rowBase]     = v0;
                *(float4*)&S[jl + j][rowBase + 4] = v1;
            }
        }
        __syncthreads();
        // 16 rows x 128 floats = 512 float4; 256 threads write 2 each.
        #pragma unroll
        for (int q = 0; q < 2; q++) {
            int idx = tid * 2 + q;
            int mr = idx >> 5;            // 0..15
            int fc = idx & 31;            // float4 column
            size_t grow = (size_t)bj * TILE + (c << 4) + mr;
            *(float4*)(out + grow * (size_t)N + (size_t)bi * TILE + fc * 4) =
                *(const float4*)&S[mr][fc * 4];
        }
    }
}

// ---------------------------------------------------------------------------
// Cosine similarity + running argmax. grid (NSPLIT, N/128).
// ---------------------------------------------------------------------------
__global__ void __launch_bounds__(256, 2) cos_kernel(int N, int V) {
    __shared__ float As[KB][TILE];
    __shared__ float Bs[KB][TILE];

    int tid = threadIdx.x;
    int rowBase = (tid >> 4) << 3;
    int colBase = (tid & 15) << 3;
    int bi = blockIdx.y;
    int split = blockIdx.x;
    int colsPerSplit = V / NSPLIT;
    int tilesPerSplit = colsPerSplit / TILE;

    const float* A = g_zn + (size_t)bi * TILE * KDIM;

    float bestv[8];
    int   besti[8];
    #pragma unroll
    for (int i = 0; i < 8; i++) { bestv[i] = -2.0f; besti[i] = 0; }

    for (int ct = 0; ct < tilesPerSplit; ct++) {
        int cbase = split * colsPerSplit + ct * TILE;
        const float* B = g_en + (size_t)cbase * KDIM;

        float acc[8][8];
        #pragma unroll
        for (int i = 0; i < 8; i++)
            #pragma unroll
            for (int j = 0; j < 8; j++) acc[i][j] = 0.f;

        gemm_tile_128(A, B, acc, As, Bs, tid, rowBase, colBase);

        #pragma unroll
        for (int i = 0; i < 8; i++) {
            #pragma unroll
            for (int j = 0; j < 8; j++) {
                int idx = cbase + colBase + j;
                if (acc[i][j] > bestv[i]) { bestv[i] = acc[i][j]; besti[i] = idx; }
            }
        }
    }

    #pragma unroll
    for (int i = 0; i < 8; i++) {
        float v = bestv[i];
        int   id = besti[i];
        #pragma unroll
        for (int off = 8; off; off >>= 1) {
            float v2 = __shfl_down_sync(0xffffffffu, v, off, 16);
            int   i2 = __shfl_down_sync(0xffffffffu, id, off, 16);
            if (v2 > v || (v2 == v && i2 < id)) { v = v2; id = i2; }
        }
        if ((tid & 15) == 0) {
            int row = bi * TILE + rowBase + i;
            g_bestval[row * NSPLIT + split] = v;
            g_bestidx[row * NSPLIT + split] = id;
        }
    }
}

__global__ void argmax_final_kernel(float* __restrict__ out, int N) {
    int row = blockIdx.x * blockDim.x + threadIdx.x;
    if (row >= N) return;
    float bv = -3.0f;
    int bi = 0;
    #pragma unroll
    for (int s = 0; s < NSPLIT; s++) {
        float v = g_bestval[row * NSPLIT + s];
        int   id = g_bestidx[row * NSPLIT + s];
        if (v > bv) { bv = v; bi = id; }
    }
    out[(size_t)N * (size_t)N + row] = (float)bi;
}

// ---------------------------------------------------------------------------
extern "C" void kernel_launch(void* const* d_in, const int* in_sizes, int n_in,
                              void* d_out, int out_size) {
    const float* z = (const float*)d_in[0];
    const float* e = (const float*)d_in[1];
    float* out = (float*)d_out;

    int N = in_sizes[0] / KDIM;   // 8192
    int V = in_sizes[1] / KDIM;   // 4096
    int T = N / TILE;             // 64

    normalize_kernel<<<N + V, 256>>>(z, e, N, V);

    int nTiles = T * (T + 1) / 2; // 2080
    adj_sym_kernel<<<nTiles, 256>>>(z, out, N);

    dim3 gCos(NSPLIT, N / TILE);
    cos_kernel<<<gCos, 256>>>(N, V);

    argmax_final_kernel<<<(N + 255) / 256, 256>>>(out, N);
}

// round 6
// speedup vs baseline: 2.4869x; 1.9202x over previous
#include <cuda_runtime.h>
#include <cuda_bf16.h>
#include <math.h>

// z [8192,256] f32, embedding [4096,256] f32.
// out = [ sigmoid(z z^T) (8192x8192 f32) , argmax cosine indices (8192 f32) ]
// GEMMs on tensor cores via bf16 split (A*B ~= Ah*Bh + Ah*Bl + Al*Bh).
// Argmax: approx filter (wide margin) + rescore with a SEQUENTIAL f32 fmaf
// chain (identical summation order to the round-1 kernel that matched the
// reference bit-for-bit at every decisive comparison).

#define KDIM 256
#define TILE 128
#define KB   32
#define NMAX 8192
#define VMAX 4096
#define AST  40          // smem row stride in bf16
#define SST  132         // mirror-staging row stride in f32
#define MARGIN 5.0e-4f   // >= 16x the ~3e-5 split-bf16 dot error bound
#define MAXCAND 256

__device__ __nv_bfloat16 g_zh [NMAX * KDIM];
__device__ __nv_bfloat16 g_zl [NMAX * KDIM];
__device__ __nv_bfloat16 g_znh[NMAX * KDIM];
__device__ __nv_bfloat16 g_znl[NMAX * KDIM];
__device__ __nv_bfloat16 g_enh[VMAX * KDIM];
__device__ __nv_bfloat16 g_enl[VMAX * KDIM];
__device__ float g_znf[NMAX * KDIM];
__device__ float g_enf[VMAX * KDIM];
__device__ float g_cos[(size_t)NMAX * VMAX];

// ---------------------------------------------------------------------------
__global__ void prep_kernel(const float* __restrict__ z,
                            const float* __restrict__ e,
                            int N, int V) {
    int row = blockIdx.x;
    int tid = threadIdx.x;
    bool isZ = row < N;
    const float* src = isZ ? (z + (size_t)row * KDIM)
                           : (e + (size_t)(row - N) * KDIM);
    float v = src[tid];

    float ss = v * v;
    #pragma unroll
    for (int o = 16; o; o >>= 1) ss += __shfl_xor_sync(0xffffffffu, ss, o);
    __shared__ float s_partial[8];
    __shared__ float s_total;
    if ((tid & 31) == 0) s_partial[tid >> 5] = ss;
    __syncthreads();
    if (tid == 0) {
        float t = 0.f;
        #pragma unroll
        for (int i = 0; i < 8; i++) t += s_partial[i];
        s_total = t;
    }
    __syncthreads();
    float inv = 1.0f / fmaxf(sqrtf(s_total), 1e-8f);
    float vn = v * inv;

    if (isZ) {
        size_t o = (size_t)row * KDIM + tid;
        __nv_bfloat16 h = __float2bfloat16(v);
        g_zh[o] = h;
        g_zl[o] = __float2bfloat16(v - __bfloat162float(h));
        __nv_bfloat16 hn = __float2bfloat16(vn);
        g_znh[o] = hn;
        g_znl[o] = __float2bfloat16(vn - __bfloat162float(hn));
        g_znf[o] = vn;
    } else {
        size_t o = (size_t)(row - N) * KDIM + tid;
        __nv_bfloat16 hn = __float2bfloat16(vn);
        g_enh[o] = hn;
        g_enl[o] = __float2bfloat16(vn - __bfloat162float(hn));
        g_enf[o] = vn;
    }
}

// ---------------------------------------------------------------------------
__device__ __forceinline__ void mma_bf16(float c[4], const unsigned a[4],
                                         const unsigned b[2]) {
    asm volatile(
        "mma.sync.aligned.m16n8k16.row.col.f32.bf16.bf16.f32 "
        "{%0,%1,%2,%3}, {%4,%5,%6,%7}, {%8,%9}, {%0,%1,%2,%3};"
        : "+f"(c[0]), "+f"(c[1]), "+f"(c[2]), "+f"(c[3])
        : "r"(a[0]), "r"(a[1]), "r"(a[2]), "r"(a[3]), "r"(b[0]), "r"(b[1]));
}

#define U32AT(arr, r, k) (*(const unsigned*)&(arr)[r][k])

__device__ __forceinline__ void mma_tile_128(
    const __nv_bfloat16* __restrict__ aH, const __nv_bfloat16* __restrict__ aL,
    const __nv_bfloat16* __restrict__ bH, const __nv_bfloat16* __restrict__ bL,
    float acc[4][4][4],
    __nv_bfloat16 (*Ah)[AST], __nv_bfloat16 (*Al)[AST],
    __nv_bfloat16 (*Bh)[AST], __nv_bfloat16 (*Bl)[AST],
    int tid) {

    int warp = tid >> 5, lane = tid & 31;
    int g = lane >> 2, t = lane & 3;
    int wm = (warp >> 2) * 64;
    int wn = (warp & 3) * 32;
    int lrow = tid >> 1;
    int lk = (tid & 1) * 16;

    for (int kc = 0; kc < KDIM; kc += KB) {
        size_t goff = (size_t)lrow * KDIM + kc + lk;
        *(uint4*)&Ah[lrow][lk]     = *(const uint4*)(aH + goff);
        *(uint4*)&Ah[lrow][lk + 8] = *(const uint4*)(aH + goff + 8);
        *(uint4*)&Al[lrow][lk]     = *(const uint4*)(aL + goff);
        *(uint4*)&Al[lrow][lk + 8] = *(const uint4*)(aL + goff + 8);
        *(uint4*)&Bh[lrow][lk]     = *(const uint4*)(bH + goff);
        *(uint4*)&Bh[lrow][lk + 8] = *(const uint4*)(bH + goff + 8);
        *(uint4*)&Bl[lrow][lk]     = *(const uint4*)(bL + goff);
        *(uint4*)&Bl[lrow][lk + 8] = *(const uint4*)(bL + goff + 8);
        __syncthreads();

        #pragma unroll
        for (int ks = 0; ks < 2; ks++) {
            int k0 = ks * 16;
            unsigned ah[4][4], al[4][4], bh[4][2], bl[4][2];
            #pragma unroll
            for (int ma = 0; ma < 4; ma++) {
                int r0 = wm + ma * 16 + g;
                ah[ma][0] = U32AT(Ah, r0,     k0 + 2 * t);
                ah[ma][1] = U32AT(Ah, r0 + 8, k0 + 2 * t);
                ah[ma][2] = U32AT(Ah, r0,     k0 + 2 * t + 8);
                ah[ma][3] = U32AT(Ah, r0 + 8, k0 + 2 * t + 8);
                al[ma][0] = U32AT(Al, r0,     k0 + 2 * t);
                al[ma][1] = U32AT(Al, r0 + 8, k0 + 2 * t);
                al[ma][2] = U32AT(Al, r0,     k0 + 2 * t + 8);
                al[ma][3] = U32AT(Al, r0 + 8, k0 + 2 * t + 8);
            }
            #pragma unroll
            for (int nb = 0; nb < 4; nb++) {
                int c0 = wn + nb * 8 + g;
                bh[nb][0] = U32AT(Bh, c0, k0 + 2 * t);
                bh[nb][1] = U32AT(Bh, c0, k0 + 2 * t + 8);
                bl[nb][0] = U32AT(Bl, c0, k0 + 2 * t);
                bl[nb][1] = U32AT(Bl, c0, k0 + 2 * t + 8);
            }
            #pragma unroll
            for (int ma = 0; ma < 4; ma++)
                #pragma unroll
                for (int nb = 0; nb < 4; nb++) {
                    mma_bf16(acc[ma][nb], ah[ma], bh[nb]);
                    mma_bf16(acc[ma][nb], ah[ma], bl[nb]);
                    mma_bf16(acc[ma][nb], al[ma], bh[nb]);
                }
        }
        __syncthreads();
    }
}

// ---------------------------------------------------------------------------
__global__ void __launch_bounds__(256) adj_sym_kernel(float* __restrict__ out, int N) {
    __shared__ __align__(16) unsigned char smem_raw[4 * TILE * AST * 2];
    __nv_bfloat16 (*Ah)[AST] = (__nv_bfloat16(*)[AST])(smem_raw);
    __nv_bfloat16 (*Al)[AST] = (__nv_bfloat16(*)[AST])(smem_raw + 1 * TILE * AST * 2);
    __nv_bfloat16 (*Bh)[AST] = (__nv_bfloat16(*)[AST])(smem_raw + 2 * TILE * AST * 2);
    __nv_bfloat16 (*Bl)[AST] = (__nv_bfloat16(*)[AST])(smem_raw + 3 * TILE * AST * 2);
    float (*S)[SST] = (float(*)[SST])smem_raw;

    const int T = N / TILE;
    int tt = blockIdx.x;
    int bi = 0;
    while (tt >= (T - bi)) { tt -= (T - bi); bi++; }
    int bj = bi + tt;

    int tid = threadIdx.x;
    int warp = tid >> 5, lane = tid & 31;
    int g = lane >> 2, t = lane & 3;
    int wm = (warp >> 2) * 64;
    int wn = (warp & 3) * 32;

    float acc[4][4][4];
    #pragma unroll
    for (int ma = 0; ma < 4; ma++)
        #pragma unroll
        for (int nb = 0; nb < 4; nb++)
            #pragma unroll
            for (int q = 0; q < 4; q++) acc[ma][nb][q] = 0.f;

    size_t aoff = (size_t)bi * TILE * KDIM;
    size_t boff = (size_t)bj * TILE * KDIM;
    mma_tile_128(g_zh + aoff, g_zl + aoff, g_zh + boff, g_zl + boff,
                 acc, Ah, Al, Bh, Bl, tid);

    #pragma unroll
    for (int ma = 0; ma < 4; ma++)
        #pragma unroll
        for (int nb = 0; nb < 4; nb++)
            #pragma unroll
            for (int q = 0; q < 4; q++)
                acc[ma][nb][q] = __fdividef(1.0f, 1.0f + __expf(-acc[ma][nb][q]));

    #pragma unroll
    for (int ma = 0; ma < 4; ma++) {
        size_t r0 = (size_t)bi * TILE + wm + ma * 16 + g;
        #pragma unroll
        for (int nb = 0; nb < 4; nb++) {
            size_t c = (size_t)bj * TILE + wn + nb * 8 + 2 * t;
            *(float2*)(out + r0 * N + c)       = make_float2(acc[ma][nb][0], acc[ma][nb][1]);
            *(float2*)(out + (r0 + 8) * N + c) = make_float2(acc[ma][nb][2], acc[ma][nb][3]);
        }
    }

    if (bi == bj) return;

    int myHalf = (warp & 3) >> 1;
    #pragma unroll
    for (int ch = 0; ch < 2; ch++) {
        __syncthreads();
        if (myHalf == ch) {
            int cl = (warp & 1) * 32;
            #pragma unroll
            for (int ma = 0; ma < 4; ma++) {
                int r = wm + ma * 16 + g;
                #pragma unroll
                for (int nb = 0; nb < 4; nb++) {
                    int c = cl + nb * 8 + 2 * t;
                    S[c][r]         = acc[ma][nb][0];
                    S[c + 1][r]     = acc[ma][nb][1];
                    S[c][r + 8]     = acc[ma][nb][2];
                    S[c + 1][r + 8] = acc[ma][nb][3];
                }
            }
        }
        __syncthreads();
        #pragma unroll
        for (int q = 0; q < 8; q++) {
            int idx = tid + 256 * q;
            int mr = idx >> 5;
            int fc = idx & 31;
            size_t grow = (size_t)bj * TILE + ch * 64 + mr;
            *(float4*)(out + grow * N + (size_t)bi * TILE + fc * 4) =
                *(const float4*)&S[mr][fc * 4];
        }
    }
}

// ---------------------------------------------------------------------------
__global__ void __launch_bounds__(256) cos_kernel(int N, int V) {
    __shared__ __align__(16) unsigned char smem_raw[4 * TILE * AST * 2];
    __nv_bfloat16 (*Ah)[AST] = (__nv_bfloat16(*)[AST])(smem_raw);
    __nv_bfloat16 (*Al)[AST] = (__nv_bfloat16(*)[AST])(smem_raw + 1 * TILE * AST * 2);
    __nv_bfloat16 (*Bh)[AST] = (__nv_bfloat16(*)[AST])(smem_raw + 2 * TILE * AST * 2);
    __nv_bfloat16 (*Bl)[AST] = (__nv_bfloat16(*)[AST])(smem_raw + 3 * TILE * AST * 2);

    int tid = threadIdx.x;
    int warp = tid >> 5, lane = tid & 31;
    int g = lane >> 2, t = lane & 3;
    int wm = (warp >> 2) * 64;
    int wn = (warp & 3) * 32;

    int bi = blockIdx.y;
    int bj = blockIdx.x;

    float acc[4][4][4];
    #pragma unroll
    for (int ma = 0; ma < 4; ma++)
        #pragma unroll
        for (int nb = 0; nb < 4; nb++)
            #pragma unroll
            for (int q = 0; q < 4; q++) acc[ma][nb][q] = 0.f;

    size_t aoff = (size_t)bi * TILE * KDIM;
    size_t boff = (size_t)bj * TILE * KDIM;
    mma_tile_128(g_znh + aoff, g_znl + aoff, g_enh + boff, g_enl + boff,
                 acc, Ah, Al, Bh, Bl, tid);

    #pragma unroll
    for (int ma = 0; ma < 4; ma++) {
        size_t r0 = (size_t)bi * TILE + wm + ma * 16 + g;
        #pragma unroll
        for (int nb = 0; nb < 4; nb++) {
            size_t c = (size_t)bj * TILE + wn + nb * 8 + 2 * t;
            *(float2*)(g_cos + r0 * V + c)       = make_float2(acc[ma][nb][0], acc[ma][nb][1]);
            *(float2*)(g_cos + (r0 + 8) * V + c) = make_float2(acc[ma][nb][2], acc[ma][nb][3]);
        }
    }
}

// ---------------------------------------------------------------------------
// Rescore: approx-max -> candidates within MARGIN -> exact dot recomputed as
// a strictly SEQUENTIAL f32 fmaf chain (k ascending), smallest-index tie-break.
// ---------------------------------------------------------------------------
__global__ void __launch_bounds__(256) rescore_kernel(float* __restrict__ out,
                                                      int N, int V) {
    int row = blockIdx.x;
    int tid = threadIdx.x;
    const float* crow = g_cos + (size_t)row * V;

    __shared__ float s_partial[8];
    __shared__ float s_val;
    __shared__ int   s_cnt;
    __shared__ int   s_cand[MAXCAND];
    __shared__ float s_z[KDIM];
    __shared__ float s_e[KDIM];
    __shared__ float s_bestv;
    __shared__ int   s_besti;

    // stage z row
    s_z[tid] = g_znf[(size_t)row * KDIM + tid];

    // 1) approx row max
    float m = -2.0f;
    for (int c = tid; c < V; c += 256) m = fmaxf(m, crow[c]);
    #pragma unroll
    for (int o = 16; o; o >>= 1) m = fmaxf(m, __shfl_xor_sync(0xffffffffu, m, o));
    if ((tid & 31) == 0) s_partial[tid >> 5] = m;
    if (tid == 0) { s_cnt = 0; s_bestv = -3.0f; s_besti = 0x7fffffff; }
    __syncthreads();
    if (tid == 0) {
        float t = s_partial[0];
        #pragma unroll
        for (int i = 1; i < 8; i++) t = fmaxf(t, s_partial[i]);
        s_val = t;
    }
    __syncthreads();
    float thr = s_val - MARGIN;

    // 2) gather candidates
    for (int c = tid; c < V; c += 256) {
        if (crow[c] >= thr) {
            int pos = atomicAdd(&s_cnt, 1);
            if (pos < MAXCAND) s_cand[pos] = c;
        }
    }
    __syncthreads();
    int nc = min(s_cnt, MAXCAND);

    // 3) exact sequential-chain re-evaluation, one candidate at a time
    for (int i = 0; i < nc; i++) {
        int c = s_cand[i];
        s_e[tid] = g_enf[(size_t)c * KDIM + tid];
        __syncthreads();
        if (tid == 0) {
            float d = 0.f;
            #pragma unroll 8
            for (int k = 0; k < KDIM; k++) d = fmaf(s_z[k], s_e[k], d);
            // strict >, tie -> smaller index (first occurrence, order-free)
            if (d > s_bestv || (d == s_bestv && c < s_besti)) {
                s_bestv = d; s_besti = c;
            }
        }
        __syncthreads();
    }

    if (tid == 0) out[(size_t)N * (size_t)N + row] = (float)s_besti;
}

// ---------------------------------------------------------------------------
extern "C" void kernel_launch(void* const* d_in, const int* in_sizes, int n_in,
                              void* d_out, int out_size) {
    const float* z = (const float*)d_in[0];
    const float* e = (const float*)d_in[1];
    float* out = (float*)d_out;

    int N = in_sizes[0] / KDIM;   // 8192
    int V = in_sizes[1] / KDIM;   // 4096
    int T = N / TILE;             // 64

    prep_kernel<<<N + V, 256>>>(z, e, N, V);

    int nTiles = T * (T + 1) / 2; // 2080
    adj_sym_kernel<<<nTiles, 256>>>(out, N);

    dim3 gCos(V / TILE, N / TILE);
    cos_kernel<<<gCos, 256>>>(N, V);

    rescore_kernel<<<N, 256>>>(out, N, V);
}

// round 8
// speedup vs baseline: 2.8771x; 1.1569x over previous
#include <cuda_runtime.h>
#include <cuda_bf16.h>
#include <math.h>

// z [8192,256] f32, embedding [4096,256] f32.
// out = [ sigmoid(z z^T) (8192x8192 f32) , argmax cosine indices (8192 f32) ]
// adj: mma.sync bf16 3-term split + FMA-only sigmoid, symmetric tiles.
// cos: mma.sync bf16 1-term (hi only) -> approx matrix; exact rescore with
//      sequential-fmaf-chain dots (order matches reference) fixes argmax.
// NOTE: tcgen05 is NOT available (harness builds PTX for compute_103, no 'a').

#define KDIM 256
#define TILE 128
#define NMAX 8192
#define VMAX 4096
#define AST  40          // smem row stride in bf16
#define SST  132         // mirror-staging row stride in f32
#define MARGIN 1.0e-2f   // > 2x the 3.9e-3 worst-case 1-term bf16 dot error
#define MAXCAND 256

__device__ __nv_bfloat16 g_zh [NMAX * KDIM];
__device__ __nv_bfloat16 g_zl [NMAX * KDIM];
__device__ __nv_bfloat16 g_znh[NMAX * KDIM];
__device__ __nv_bfloat16 g_enh[VMAX * KDIM];
__device__ float g_znf[NMAX * KDIM];
__device__ float g_enf[VMAX * KDIM];
__device__ float g_cos[(size_t)NMAX * VMAX];

// ===================== FMA-only sigmoid (no MUFU) ===========================
__device__ __forceinline__ float sigmoid_fast(float x) {
    float ax = fminf(fabsf(x), 30.0f);
    float u  = ax * 1.4426950408889634f;          // exp(-|x|) = 2^{-u}
    float fm = u + 12582912.0f;                   // round-to-nearest trick
    float n  = fm - 12582912.0f;
    float f  = n - u;                             // f in [-0.5, 0.5]
    float p  = 1.3333558146428443e-3f;            // 2^f minimax deg-5
    p = fmaf(p, f, 9.6181291976353954e-3f);
    p = fmaf(p, f, 5.5504108664798463e-2f);
    p = fmaf(p, f, 2.4022650695910071e-1f);
    p = fmaf(p, f, 6.9314718055994531e-1f);
    p = fmaf(p, f, 1.0f);
    int nbits = (__float_as_int(fm) & 0x7F) << 23;      // n in [0,128)
    float scale = __int_as_float(0x3F800000 - nbits);   // 2^{-n}
    float q = p * scale;                          // e^{-|x|} in (0,1]
    float d = 1.0f + q;
    float r = fmaf(d, fmaf(d, 0.33333333f, -1.5f), 2.16666667f);  // ~1/d
    r = r * (2.0f - d * r);                       // 2x Newton -> ~1e-7 rel
    r = r * (2.0f - d * r);
    return (x >= 0.0f) ? r : r * q;
}

// ===================== prep: normalize + bf16 split =========================
__global__ void prep_kernel(const float* __restrict__ z,
                            const float* __restrict__ e,
                            int N, int V) {
    int row = blockIdx.x;
    int tid = threadIdx.x;
    bool isZ = row < N;
    const float* src = isZ ? (z + (size_t)row * KDIM)
                           : (e + (size_t)(row - N) * KDIM);
    float v = src[tid];

    float ss = v * v;
    #pragma unroll
    for (int o = 16; o; o >>= 1) ss += __shfl_xor_sync(0xffffffffu, ss, o);
    __shared__ float s_partial[8];
    __shared__ float s_total;
    if ((tid & 31) == 0) s_partial[tid >> 5] = ss;
    __syncthreads();
    if (tid == 0) {
        float t = 0.f;
        #pragma unroll
        for (int i = 0; i < 8; i++) t += s_partial[i];
        s_total = t;
    }
    __syncthreads();
    float inv = 1.0f / fmaxf(sqrtf(s_total), 1e-8f);
    float vn = v * inv;

    if (isZ) {
        size_t o = (size_t)row * KDIM + tid;
        __nv_bfloat16 h = __float2bfloat16(v);
        g_zh[o] = h;
        g_zl[o] = __float2bfloat16(v - __bfloat162float(h));
        g_znh[o] = __float2bfloat16(vn);
        g_znf[o] = vn;
    } else {
        size_t o = (size_t)(row - N) * KDIM + tid;
        g_enh[o] = __float2bfloat16(vn);
        g_enf[o] = vn;
    }
}

// ---------------------------------------------------------------------------
__device__ __forceinline__ void mma_bf16(float c[4], const unsigned a[4],
                                         const unsigned b[2]) {
    asm volatile(
        "mma.sync.aligned.m16n8k16.row.col.f32.bf16.bf16.f32 "
        "{%0,%1,%2,%3}, {%4,%5,%6,%7}, {%8,%9}, {%0,%1,%2,%3};"
        : "+f"(c[0]), "+f"(c[1]), "+f"(c[2]), "+f"(c[3])
        : "r"(a[0]), "r"(a[1]), "r"(a[2]), "r"(a[3]), "r"(b[0]), "r"(b[1]));
}

#define U32AT(arr, r, k) (*(const unsigned*)&(arr)[r][k])

// 3-term 128x128 tile GEMM over K=256: acc += Ah*Bh + Ah*Bl + Al*Bh.
__device__ __forceinline__ void mma_tile_128_3t(
    const __nv_bfloat16* __restrict__ aH, const __nv_bfloat16* __restrict__ aL,
    const __nv_bfloat16* __restrict__ bH, const __nv_bfloat16* __restrict__ bL,
    float acc[4][4][4],
    __nv_bfloat16 (*Ah)[AST], __nv_bfloat16 (*Al)[AST],
    __nv_bfloat16 (*Bh)[AST], __nv_bfloat16 (*Bl)[AST],
    int tid) {

    int warp = tid >> 5, lane = tid & 31;
    int g = lane >> 2, t = lane & 3;
    int wm = (warp >> 2) * 64;
    int wn = (warp & 3) * 32;
    int lrow = tid >> 1;
    int lk = (tid & 1) * 16;

    for (int kc = 0; kc < KDIM; kc += 32) {
        size_t goff = (size_t)lrow * KDIM + kc + lk;
        *(uint4*)&Ah[lrow][lk]     = *(const uint4*)(aH + goff);
        *(uint4*)&Ah[lrow][lk + 8] = *(const uint4*)(aH + goff + 8);
        *(uint4*)&Al[lrow][lk]     = *(const uint4*)(aL + goff);
        *(uint4*)&Al[lrow][lk + 8] = *(const uint4*)(aL + goff + 8);
        *(uint4*)&Bh[lrow][lk]     = *(const uint4*)(bH + goff);
        *(uint4*)&Bh[lrow][lk + 8] = *(const uint4*)(bH + goff + 8);
        *(uint4*)&Bl[lrow][lk]     = *(const uint4*)(bL + goff);
        *(uint4*)&Bl[lrow][lk + 8] = *(const uint4*)(bL + goff + 8);
        __syncthreads();

        #pragma unroll
        for (int ks = 0; ks < 2; ks++) {
            int k0 = ks * 16;
            unsigned ah[4][4], al[4][4], bh[4][2], bl[4][2];
            #pragma unroll
            for (int ma = 0; ma < 4; ma++) {
                int r0 = wm + ma * 16 + g;
                ah[ma][0] = U32AT(Ah, r0,     k0 + 2 * t);
                ah[ma][1] = U32AT(Ah, r0 + 8, k0 + 2 * t);
                ah[ma][2] = U32AT(Ah, r0,     k0 + 2 * t + 8);
                ah[ma][3] = U32AT(Ah, r0 + 8, k0 + 2 * t + 8);
                al[ma][0] = U32AT(Al, r0,     k0 + 2 * t);
                al[ma][1] = U32AT(Al, r0 + 8, k0 + 2 * t);
                al[ma][2] = U32AT(Al, r0,     k0 + 2 * t + 8);
                al[ma][3] = U32AT(Al, r0 + 8, k0 + 2 * t + 8);
            }
            #pragma unroll
            for (int nb = 0; nb < 4; nb++) {
                int c0 = wn + nb * 8 + g;
                bh[nb][0] = U32AT(Bh, c0, k0 + 2 * t);
                bh[nb][1] = U32AT(Bh, c0, k0 + 2 * t + 8);
                bl[nb][0] = U32AT(Bl, c0, k0 + 2 * t);
                bl[nb][1] = U32AT(Bl, c0, k0 + 2 * t + 8);
            }
            #pragma unroll
            for (int ma = 0; ma < 4; ma++)
                #pragma unroll
                for (int nb = 0; nb < 4; nb++) {
                    mma_bf16(acc[ma][nb], ah[ma], bh[nb]);
                    mma_bf16(acc[ma][nb], ah[ma], bl[nb]);
                    mma_bf16(acc[ma][nb], al[ma], bh[nb]);
                }
        }
        __syncthreads();
    }
}

// ---------------------------------------------------------------------------
// adj: upper-triangular tiles only; mirror-write off-diagonals.
// ---------------------------------------------------------------------------
__global__ void __launch_bounds__(256) adj_sym_kernel(float* __restrict__ out, int N) {
    __shared__ __align__(16) unsigned char smem_raw[4 * TILE * AST * 2];
    __nv_bfloat16 (*Ah)[AST] = (__nv_bfloat16(*)[AST])(smem_raw);
    __nv_bfloat16 (*Al)[AST] = (__nv_bfloat16(*)[AST])(smem_raw + 1 * TILE * AST * 2);
    __nv_bfloat16 (*Bh)[AST] = (__nv_bfloat16(*)[AST])(smem_raw + 2 * TILE * AST * 2);
    __nv_bfloat16 (*Bl)[AST] = (__nv_bfloat16(*)[AST])(smem_raw + 3 * TILE * AST * 2);
    float (*S)[SST] = (float(*)[SST])smem_raw;

    const int T = N / TILE;
    int tt = blockIdx.x;
    int bi = 0;
    while (tt >= (T - bi)) { tt -= (T - bi); bi++; }
    int bj = bi + tt;

    int tid = threadIdx.x;
    int warp = tid >> 5, lane = tid & 31;
    int g = lane >> 2, t = lane & 3;
    int wm = (warp >> 2) * 64;
    int wn = (warp & 3) * 32;

    float acc[4][4][4];
    #pragma unroll
    for (int ma = 0; ma < 4; ma++)
        #pragma unroll
        for (int nb = 0; nb < 4; nb++)
            #pragma unroll
            for (int q = 0; q < 4; q++) acc[ma][nb][q] = 0.f;

    size_t aoff = (size_t)bi * TILE * KDIM;
    size_t boff = (size_t)bj * TILE * KDIM;
    mma_tile_128_3t(g_zh + aoff, g_zl + aoff, g_zh + boff, g_zl + boff,
                    acc, Ah, Al, Bh, Bl, tid);

    // FMA-only sigmoid (no MUFU).
    #pragma unroll
    for (int ma = 0; ma < 4; ma++)
        #pragma unroll
        for (int nb = 0; nb < 4; nb++)
            #pragma unroll
            for (int q = 0; q < 4; q++)
                acc[ma][nb][q] = sigmoid_fast(acc[ma][nb][q]);

    #pragma unroll
    for (int ma = 0; ma < 4; ma++) {
        size_t r0 = (size_t)bi * TILE + wm + ma * 16 + g;
        #pragma unroll
        for (int nb = 0; nb < 4; nb++) {
            size_t c = (size_t)bj * TILE + wn + nb * 8 + 2 * t;
            *(float2*)(out + r0 * N + c)       = make_float2(acc[ma][nb][0], acc[ma][nb][1]);
            *(float2*)(out + (r0 + 8) * N + c) = make_float2(acc[ma][nb][2], acc[ma][nb][3]);
        }
    }

    if (bi == bj) return;

    int myHalf = (warp & 3) >> 1;
    #pragma unroll
    for (int ch = 0; ch < 2; ch++) {
        __syncthreads();
        if (myHalf == ch) {
            int cl = (warp & 1) * 32;
            #pragma unroll
            for (int ma = 0; ma < 4; ma++) {
                int r = wm + ma * 16 + g;
                #pragma unroll
                for (int nb = 0; nb < 4; nb++) {
                    int c = cl + nb * 8 + 2 * t;
                    S[c][r]         = acc[ma][nb][0];
                    S[c + 1][r]     = acc[ma][nb][1];
                    S[c][r + 8]     = acc[ma][nb][2];
                    S[c + 1][r + 8] = acc[ma][nb][3];
                }
            }
        }
        __syncthreads();
        #pragma unroll
        for (int q = 0; q < 8; q++) {
            int idx = tid + 256 * q;
            int mr = idx >> 5;
            int fc = idx & 31;
            size_t grow = (size_t)bj * TILE + ch * 64 + mr;
            *(float4*)(out + grow * N + (size_t)bi * TILE + fc * 4) =
                *(const float4*)&S[mr][fc * 4];
        }
    }
}

// ---------------------------------------------------------------------------
// cos: 1-term bf16 GEMM (hi only) -> approx cosine matrix.
// ---------------------------------------------------------------------------
__global__ void __launch_bounds__(256) cos_kernel(int N, int V) {
    __shared__ __align__(16) __nv_bfloat16 Ah[TILE][AST];
    __shared__ __align__(16) __nv_bfloat16 Bh[TILE][AST];

    int tid = threadIdx.x;
    int warp = tid >> 5, lane = tid & 31;
    int g = lane >> 2, t = lane & 3;
    int wm = (warp >> 2) * 64;
    int wn = (warp & 3) * 32;
    int bi = blockIdx.y;
    int bj = blockIdx.x;
    int lrow = tid >> 1;
    int lk = (tid & 1) * 16;

    float acc[4][4][4];
    #pragma unroll
    for (int ma = 0; ma < 4; ma++)
        #pragma unroll
        for (int nb = 0; nb < 4; nb++)
            #pragma unroll
            for (int q = 0; q < 4; q++) acc[ma][nb][q] = 0.f;

    const __nv_bfloat16* aH = g_znh + (size_t)bi * TILE * KDIM;
    const __nv_bfloat16* bH = g_enh + (size_t)bj * TILE * KDIM;

    for (int kc = 0; kc < KDIM; kc += 32) {
        size_t goff = (size_t)lrow * KDIM + kc + lk;
        *(uint4*)&Ah[lrow][lk]     = *(const uint4*)(aH + goff);
        *(uint4*)&Ah[lrow][lk + 8] = *(const uint4*)(aH + goff + 8);
        *(uint4*)&Bh[lrow][lk]     = *(const uint4*)(bH + goff);
        *(uint4*)&Bh[lrow][lk + 8] = *(const uint4*)(bH + goff + 8);
        __syncthreads();

        #pragma unroll
        for (int ks = 0; ks < 2; ks++) {
            int k0 = ks * 16;
            unsigned ah[4][4], bh[4][2];
            #pragma unroll
            for (int ma = 0; ma < 4; ma++) {
                int r0 = wm + ma * 16 + g;
                ah[ma][0] = U32AT(Ah, r0,     k0 + 2 * t);
                ah[ma][1] = U32AT(Ah, r0 + 8, k0 + 2 * t);
                ah[ma][2] = U32AT(Ah, r0,     k0 + 2 * t + 8);
                ah[ma][3] = U32AT(Ah, r0 + 8, k0 + 2 * t + 8);
            }
            #pragma unroll
            for (int nb = 0; nb < 4; nb++) {
                int c0 = wn + nb * 8 + g;
                bh[nb][0] = U32AT(Bh, c0, k0 + 2 * t);
                bh[nb][1] = U32AT(Bh, c0, k0 + 2 * t + 8);
            }
            #pragma unroll
            for (int ma = 0; ma < 4; ma++)
                #pragma unroll
                for (int nb = 0; nb < 4; nb++)
                    mma_bf16(acc[ma][nb], ah[ma], bh[nb]);
        }
        __syncthreads();
    }

    #pragma unroll
    for (int ma = 0; ma < 4; ma++) {
        size_t r0 = (size_t)bi * TILE + wm + ma * 16 + g;
        #pragma unroll
        for (int nb = 0; nb < 4; nb++) {
            size_t c = (size_t)bj * TILE + wn + nb * 8 + 2 * t;
            *(float2*)(g_cos + r0 * V + c)       = make_float2(acc[ma][nb][0], acc[ma][nb][1]);
            *(float2*)(g_cos + (r0 + 8) * V + c) = make_float2(acc[ma][nb][2], acc[ma][nb][3]);
        }
    }
}

// ---------------------------------------------------------------------------
// Exact rescore (proven in R6): approx-max -> candidates within MARGIN ->
// sequential f32 fmaf-chain dots, smallest-index tie-break.
// ---------------------------------------------------------------------------
__global__ void __launch_bounds__(256) rescore_kernel(float* __restrict__ out,
                                                      int N, int V) {
    int row = blockIdx.x;
    int tid = threadIdx.x;
    const float* crow = g_cos + (size_t)row * V;

    __shared__ float s_partial[8];
    __shared__ float s_val;
    __shared__ int   s_cnt;
    __shared__ int   s_cand[MAXCAND];
    __shared__ float s_z[KDIM];
    __shared__ float s_e[KDIM];
    __shared__ float s_bestv;
    __shared__ int   s_besti;

    s_z[tid] = g_znf[(size_t)row * KDIM + tid];

    float m = -2.0f;
    for (int c = tid; c < V; c += 256) m = fmaxf(m, crow[c]);
    #pragma unroll
    for (int o = 16; o; o >>= 1) m = fmaxf(m, __shfl_xor_sync(0xffffffffu, m, o));
    if ((tid & 31) == 0) s_partial[tid >> 5] = m;
    if (tid == 0) { s_cnt = 0; s_bestv = -3.0f; s_besti = 0x7fffffff; }
    __syncthreads();
    if (tid == 0) {
        float t = s_partial[0];
        #pragma unroll
        for (int i = 1; i < 8; i++) t = fmaxf(t, s_partial[i]);
        s_val = t;
    }
    __syncthreads();
    float thr = s_val - MARGIN;

    for (int c = tid; c < V; c += 256) {
        if (crow[c] >= thr) {
            int pos = atomicAdd(&s_cnt, 1);
            if (pos < MAXCAND) s_cand[pos] = c;
        }
    }
    __syncthreads();
    int nc = min(s_cnt, MAXCAND);

    for (int i = 0; i < nc; i++) {
        int c = s_cand[i];
        s_e[tid] = g_enf[(size_t)c * KDIM + tid];
        __syncthreads();
        if (tid == 0) {
            float d = 0.f;
            #pragma unroll 8
            for (int k = 0; k < KDIM; k++) d = fmaf(s_z[k], s_e[k], d);
            if (d > s_bestv || (d == s_bestv && c < s_besti)) {
                s_bestv = d; s_besti = c;
            }
        }
        __syncthreads();
    }

    if (tid == 0) out[(size_t)N * (size_t)N + row] = (float)s_besti;
}

// ---------------------------------------------------------------------------
extern "C" void kernel_launch(void* const* d_in, const int* in_sizes, int n_in,
                              void* d_out, int out_size) {
    const float* z = (const float*)d_in[0];
    const float* e = (const float*)d_in[1];
    float* out = (float*)d_out;

    int N = in_sizes[0] / KDIM;   // 8192
    int V = in_sizes[1] / KDIM;   // 4096
    int T = N / TILE;             // 64

    prep_kernel<<<N + V, 256>>>(z, e, N, V);

    int nTiles = T * (T + 1) / 2; // 2080
    adj_sym_kernel<<<nTiles, 256>>>(out, N);

    dim3 gCos(V / TILE, N / TILE);
    cos_kernel<<<gCos, 256>>>(N, V);

    rescore_kernel<<<N, 256>>>(out, N, V);
}

// round 10
// speedup vs baseline: 2.9068x; 1.0103x over previous
#include <cuda_runtime.h>
#include <cuda_bf16.h>
#include <math.h>

// z [8192,256] f32, embedding [4096,256] f32.
// out = [ sigmoid(z z^T) (8192x8192 f32) , argmax cosine indices (8192 f32) ]
// adj: mma.sync bf16 3-term split, cp.async double-buffered, FMA sigmoid.
// cos: mma.sync bf16 1-term, cp.async double-buffered, fused row-max atomics.
// rescore: single gather pass + exact sequential-fmaf dots (proven R6).
// NOTE: tcgen05 unavailable (harness targets compute_103 without 'a').

#define KDIM 256
#define TILE 128
#define NMAX 8192
#define VMAX 4096
#define AST  40          // smem row stride in bf16 (80B rows, 16B-aligned)
#define SST  132         // mirror-staging row stride in f32
#define MARGIN 1.0e-2f   // > 2x the 3.9e-3 worst-case 1-term bf16 dot error
#define MAXCAND 256
#define BUFB (TILE * AST * 2)   // 10240 bytes per operand buffer

__device__ __nv_bfloat16 g_zh [NMAX * KDIM];
__device__ __nv_bfloat16 g_zl [NMAX * KDIM];
__device__ __nv_bfloat16 g_znh[NMAX * KDIM];
__device__ __nv_bfloat16 g_enh[VMAX * KDIM];
__device__ float g_znf[NMAX * KDIM];
__device__ float g_enf[VMAX * KDIM];
__device__ float g_cos[(size_t)NMAX * VMAX];
__device__ unsigned g_rowmax[NMAX];   // order-preserving float encoding

// ---------------- order-preserving float <-> uint ---------------------------
__device__ __forceinline__ unsigned fenc(float f) {
    unsigned b = __float_as_uint(f);
    return (b & 0x80000000u) ? ~b : (b | 0x80000000u);
}
__device__ __forceinline__ float fdec(unsigned u) {
    return (u & 0x80000000u) ? __uint_as_float(u & 0x7FFFFFFFu)
                             : __uint_as_float(~u);
}

// ---------------- cp.async helpers ------------------------------------------
#define CP16(sa, gp) \
    asm volatile("cp.async.cg.shared.global [%0], [%1], 16;" \
                 :: "r"(sa), "l"(gp) : "memory")
#define CP_COMMIT() asm volatile("cp.async.commit_group;" ::: "memory")
#define CP_WAIT0()  asm volatile("cp.async.wait_group 0;" ::: "memory")

// ===================== FMA-only sigmoid (no MUFU) ===========================
__device__ __forceinline__ float sigmoid_fast(float x) {
    float ax = fminf(fabsf(x), 30.0f);
    float u  = ax * 1.4426950408889634f;
    float fm = u + 12582912.0f;
    float n  = fm - 12582912.0f;
    float f  = n - u;
    float p  = 1.3333558146428443e-3f;
    p = fmaf(p, f, 9.6181291976353954e-3f);
    p = fmaf(p, f, 5.5504108664798463e-2f);
    p = fmaf(p, f, 2.4022650695910071e-1f);
    p = fmaf(p, f, 6.9314718055994531e-1f);
    p = fmaf(p, f, 1.0f);
    int nbits = (__float_as_int(fm) & 0x7F) << 23;
    float scale = __int_as_float(0x3F800000 - nbits);
    float q = p * scale;
    float d = 1.0f + q;
    float r = fmaf(d, fmaf(d, 0.33333333f, -1.5f), 2.16666667f);
    r = r * (2.0f - d * r);
    r = r * (2.0f - d * r);
    return (x >= 0.0f) ? r : r * q;
}

// ===================== prep: normalize + bf16 split =========================
__global__ void prep_kernel(const float* __restrict__ z,
                            const float* __restrict__ e,
                            int N, int V) {
    int row = blockIdx.x;
    int tid = threadIdx.x;
    bool isZ = row < N;
    const float* src = isZ ? (z + (size_t)row * KDIM)
                           : (e + (size_t)(row - N) * KDIM);
    float v = src[tid];

    float ss = v * v;
    #pragma unroll
    for (int o = 16; o; o >>= 1) ss += __shfl_xor_sync(0xffffffffu, ss, o);
    __shared__ float s_partial[8];
    __shared__ float s_total;
    if ((tid & 31) == 0) s_partial[tid >> 5] = ss;
    __syncthreads();
    if (tid == 0) {
        float t = 0.f;
        #pragma unroll
        for (int i = 0; i < 8; i++) t += s_partial[i];
        s_total = t;
    }
    __syncthreads();
    float inv = 1.0f / fmaxf(sqrtf(s_total), 1e-8f);
    float vn = v * inv;

    if (isZ) {
        size_t o = (size_t)row * KDIM + tid;
        __nv_bfloat16 h = __float2bfloat16(v);
        g_zh[o] = h;
        g_zl[o] = __float2bfloat16(v - __bfloat162float(h));
        g_znh[o] = __float2bfloat16(vn);
        g_znf[o] = vn;
        if (tid == 0) g_rowmax[row] = 0u;   // reset per launch
    } else {
        size_t o = (size_t)(row - N) * KDIM + tid;
        g_enh[o] = __float2bfloat16(vn);
        g_enf[o] = vn;
    }
}

// ---------------------------------------------------------------------------
__device__ __forceinline__ void mma_bf16(float c[4], const unsigned a[4],
                                         const unsigned b[2]) {
    asm volatile(
        "mma.sync.aligned.m16n8k16.row.col.f32.bf16.bf16.f32 "
        "{%0,%1,%2,%3}, {%4,%5,%6,%7}, {%8,%9}, {%0,%1,%2,%3};"
        : "+f"(c[0]), "+f"(c[1]), "+f"(c[2]), "+f"(c[3])
        : "r"(a[0]), "r"(a[1]), "r"(a[2]), "r"(a[3]), "r"(b[0]), "r"(b[1]));
}
#define U32P(base, r, k) (*(const unsigned*)((base) + ((r) * AST + (k)) * 2))

// One 32-k chunk of the 3-term product from smem buffers.
__device__ __forceinline__ void mma_chunk_3t(
    const unsigned char* Ah, const unsigned char* Al,
    const unsigned char* Bh, const unsigned char* Bl,
    float acc[4][4][4], int wm, int wn, int g, int t) {
    #pragma unroll
    for (int ks = 0; ks < 2; ks++) {
        int k0 = ks * 16;
        unsigned ah[4][4], al[4][4], bh[4][2], bl[4][2];
        #pragma unroll
        for (int ma = 0; ma < 4; ma++) {
            int r0 = wm + ma * 16 + g;
            ah[ma][0] = U32P(Ah, r0,     k0 + 2 * t);
            ah[ma][1] = U32P(Ah, r0 + 8, k0 + 2 * t);
            ah[ma][2] = U32P(Ah, r0,     k0 + 2 * t + 8);
            ah[ma][3] = U32P(Ah, r0 + 8, k0 + 2 * t + 8);
            al[ma][0] = U32P(Al, r0,     k0 + 2 * t);
            al[ma][1] = U32P(Al, r0 + 8, k0 + 2 * t);
            al[ma][2] = U32P(Al, r0,     k0 + 2 * t + 8);
            al[ma][3] = U32P(Al, r0 + 8, k0 + 2 * t + 8);
        }
        #pragma unroll
        for (int nb = 0; nb < 4; nb++) {
            int c0 = wn + nb * 8 + g;
            bh[nb][0] = U32P(Bh, c0, k0 + 2 * t);
            bh[nb][1] = U32P(Bh, c0, k0 + 2 * t + 8);
            bl[nb][0] = U32P(Bl, c0, k0 + 2 * t);
            bl[nb][1] = U32P(Bl, c0, k0 + 2 * t + 8);
        }
        #pragma unroll
        for (int ma = 0; ma < 4; ma++)
            #pragma unroll
            for (int nb = 0; nb < 4; nb++) {
                mma_bf16(acc[ma][nb], ah[ma], bh[nb]);
                mma_bf16(acc[ma][nb], ah[ma], bl[nb]);
                mma_bf16(acc[ma][nb], al[ma], bh[nb]);
            }
    }
}

__device__ __forceinline__ void mma_chunk_1t(
    const unsigned char* Ah, const unsigned char* Bh,
    float acc[4][4][4], int wm, int wn, int g, int t) {
    #pragma unroll
    for (int ks = 0; ks < 2; ks++) {
        int k0 = ks * 16;
        unsigned ah[4][4], bh[4][2];
        #pragma unroll
        for (int ma = 0; ma < 4; ma++) {
            int r0 = wm + ma * 16 + g;
            ah[ma][0] = U32P(Ah, r0,     k0 + 2 * t);
            ah[ma][1] = U32P(Ah, r0 + 8, k0 + 2 * t);
            ah[ma][2] = U32P(Ah, r0,     k0 + 2 * t + 8);
            ah[ma][3] = U32P(Ah, r0 + 8, k0 + 2 * t + 8);
        }
        #pragma unroll
        for (int nb = 0; nb < 4; nb++) {
            int c0 = wn + nb * 8 + g;
            bh[nb][0] = U32P(Bh, c0, k0 + 2 * t);
            bh[nb][1] = U32P(Bh, c0, k0 + 2 * t + 8);
        }
        #pragma unroll
        for (int ma = 0; ma < 4; ma++)
            #pragma unroll
            for (int nb = 0; nb < 4; nb++)
                mma_bf16(acc[ma][nb], ah[ma], bh[nb]);
    }
}

// ---------------------------------------------------------------------------
// adj: upper-tri tiles, cp.async double buffer, mirror-write off-diagonals.
// ---------------------------------------------------------------------------
#define ADJ_SMEM (2 * 4 * BUFB)

__global__ void __launch_bounds__(256) adj_sym_kernel(float* __restrict__ out, int N) {
    extern __shared__ __align__(16) unsigned char dsm[];
    float (*S)[SST] = (float(*)[SST])dsm;

    const int T = N / TILE;
    int tt = blockIdx.x;
    int bi = 0;
    while (tt >= (T - bi)) { tt -= (T - bi); bi++; }
    int bj = bi + tt;

    int tid = threadIdx.x;
    int warp = tid >> 5, lane = tid & 31;
    int g = lane >> 2, t = lane & 3;
    int wm = (warp >> 2) * 64;
    int wn = (warp & 3) * 32;
    int lrow = tid >> 1;
    int lk = (tid & 1) * 16;

    const __nv_bfloat16* srcs[4] = {
        g_zh + (size_t)bi * TILE * KDIM, g_zl + (size_t)bi * TILE * KDIM,
        g_zh + (size_t)bj * TILE * KDIM, g_zl + (size_t)bj * TILE * KDIM };

    unsigned sm_row = (unsigned)((lrow * AST + lk) * 2);
    unsigned sbase = (unsigned)__cvta_generic_to_shared(dsm);

    // prologue: chunk 0 -> buffer 0
    {
        size_t goff = (size_t)lrow * KDIM + lk;
        #pragma unroll
        for (int a = 0; a < 4; a++) {
            unsigned sa = sbase + a * BUFB + sm_row;
            CP16(sa,      srcs[a] + goff);
            CP16(sa + 16, srcs[a] + goff + 8);   // +8 elements = +16 BYTES
        }
        CP_COMMIT();
    }

    float acc[4][4][4];
    #pragma unroll
    for (int ma = 0; ma < 4; ma++)
        #pragma unroll
        for (int nb = 0; nb < 4; nb++)
            #pragma unroll
            for (int q = 0; q < 4; q++) acc[ma][nb][q] = 0.f;

    for (int q = 0; q < 8; q++) {
        CP_WAIT0();
        __syncthreads();
        if (q < 7) {
            size_t goff = (size_t)lrow * KDIM + (q + 1) * 32 + lk;
            unsigned boff = ((q + 1) & 1) * 4 * BUFB;
            #pragma unroll
            for (int a = 0; a < 4; a++) {
                unsigned sa = sbase + boff + a * BUFB + sm_row;
                CP16(sa,      srcs[a] + goff);
                CP16(sa + 16, srcs[a] + goff + 8);
            }
            CP_COMMIT();
        }
        const unsigned char* b = dsm + (q & 1) * 4 * BUFB;
        mma_chunk_3t(b, b + BUFB, b + 2 * BUFB, b + 3 * BUFB,
                     acc, wm, wn, g, t);
    }

    #pragma unroll
    for (int ma = 0; ma < 4; ma++)
        #pragma unroll
        for (int nb = 0; nb < 4; nb++)
            #pragma unroll
            for (int q = 0; q < 4; q++)
                acc[ma][nb][q] = sigmoid_fast(acc[ma][nb][q]);

    #pragma unroll
    for (int ma = 0; ma < 4; ma++) {
        size_t r0 = (size_t)bi * TILE + wm + ma * 16 + g;
        #pragma unroll
        for (int nb = 0; nb < 4; nb++) {
            size_t c = (size_t)bj * TILE + wn + nb * 8 + 2 * t;
            *(float2*)(out + r0 * N + c)       = make_float2(acc[ma][nb][0], acc[ma][nb][1]);
            *(float2*)(out + (r0 + 8) * N + c) = make_float2(acc[ma][nb][2], acc[ma][nb][3]);
        }
    }

    if (bi == bj) return;

    int myHalf = (warp & 3) >> 1;
    #pragma unroll
    for (int ch = 0; ch < 2; ch++) {
        __syncthreads();
        if (myHalf == ch) {
            int cl = (warp & 1) * 32;
            #pragma unroll
            for (int ma = 0; ma < 4; ma++) {
                int r = wm + ma * 16 + g;
                #pragma unroll
                for (int nb = 0; nb < 4; nb++) {
                    int c = cl + nb * 8 + 2 * t;
                    S[c][r]         = acc[ma][nb][0];
                    S[c + 1][r]     = acc[ma][nb][1];
                    S[c][r + 8]     = acc[ma][nb][2];
                    S[c + 1][r + 8] = acc[ma][nb][3];
                }
            }
        }
        __syncthreads();
        #pragma unroll
        for (int q = 0; q < 8; q++) {
            int idx = tid + 256 * q;
            int mr = idx >> 5;
            int fc = idx & 31;
            size_t grow = (size_t)bj * TILE + ch * 64 + mr;
            *(float4*)(out + grow * N + (size_t)bi * TILE + fc * 4) =
                *(const float4*)&S[mr][fc * 4];
        }
    }
}

// ---------------------------------------------------------------------------
// cos: 1-term bf16 GEMM, cp.async double buffer, fused per-row atomic max.
// ---------------------------------------------------------------------------
__global__ void __launch_bounds__(256) cos_kernel(int N, int V) {
    __shared__ __align__(16) unsigned char csm[2 * 2 * BUFB];

    int tid = threadIdx.x;
    int warp = tid >> 5, lane = tid & 31;
    int g = lane >> 2, t = lane & 3;
    int wm = (warp >> 2) * 64;
    int wn = (warp & 3) * 32;
    int bi = blockIdx.y;
    int bj = blockIdx.x;
    int lrow = tid >> 1;
    int lk = (tid & 1) * 16;

    const __nv_bfloat16* srcs[2] = {
        g_znh + (size_t)bi * TILE * KDIM, g_enh + (size_t)bj * TILE * KDIM };

    unsigned sm_row = (unsigned)((lrow * AST + lk) * 2);
    unsigned sbase = (unsigned)__cvta_generic_to_shared(csm);

    {
        size_t goff = (size_t)lrow * KDIM + lk;
        #pragma unroll
        for (int a = 0; a < 2; a++) {
            unsigned sa = sbase + a * BUFB + sm_row;
            CP16(sa,      srcs[a] + goff);
            CP16(sa + 16, srcs[a] + goff + 8);
        }
        CP_COMMIT();
    }

    float acc[4][4][4];
    #pragma unroll
    for (int ma = 0; ma < 4; ma++)
        #pragma unroll
        for (int nb = 0; nb < 4; nb++)
            #pragma unroll
            for (int q = 0; q < 4; q++) acc[ma][nb][q] = 0.f;

    for (int q = 0; q < 8; q++) {
        CP_WAIT0();
        __syncthreads();
        if (q < 7) {
            size_t goff = (size_t)lrow * KDIM + (q + 1) * 32 + lk;
            unsigned boff = ((q + 1) & 1) * 2 * BUFB;
            #pragma unroll
            for (int a = 0; a < 2; a++) {
                unsigned sa = sbase + boff + a * BUFB + sm_row;
                CP16(sa,      srcs[a] + goff);
                CP16(sa + 16, srcs[a] + goff + 8);
            }
            CP_COMMIT();
        }
        const unsigned char* b = csm + (q & 1) * 2 * BUFB;
        mma_chunk_1t(b, b + BUFB, acc, wm, wn, g, t);
    }

    #pragma unroll
    for (int ma = 0; ma < 4; ma++) {
        size_t r0 = (size_t)bi * TILE + wm + ma * 16 + g;
        #pragma unroll
        for (int nb = 0; nb < 4; nb++) {
            size_t c = (size_t)bj * TILE + wn + nb * 8 + 2 * t;
            *(float2*)(g_cos + r0 * V + c)       = make_float2(acc[ma][nb][0], acc[ma][nb][1]);
            *(float2*)(g_cos + (r0 + 8) * V + c) = make_float2(acc[ma][nb][2], acc[ma][nb][3]);
        }
        #pragma unroll
        for (int h = 0; h < 2; h++) {
            float m = -2.0f;
            #pragma unroll
            for (int nb = 0; nb < 4; nb++) {
                m = fmaxf(m, acc[ma][nb][h * 2 + 0]);
                m = fmaxf(m, acc[ma][nb][h * 2 + 1]);
            }
            #pragma unroll
            for (int off = 2; off; off >>= 1)
                m = fmaxf(m, __shfl_xor_sync(0xffffffffu, m, off, 4));
            if (t == 0)
                atomicMax(&g_rowmax[r0 + h * 8], fenc(m));
        }
    }
}

// ---------------------------------------------------------------------------
// Rescore: single gather pass (threshold from g_rowmax) + exact sequential
// fmaf-chain dots, smallest-index tie-break.
// ---------------------------------------------------------------------------
__global__ void __launch_bounds__(256) rescore_kernel(float* __restrict__ out,
                                                      int N, int V) {
    int row = blockIdx.x;
    int tid = threadIdx.x;
    const float* crow = g_cos + (size_t)row * V;

    __shared__ int   s_cnt;
    __shared__ int   s_cand[MAXCAND];
    __shared__ float s_z[KDIM];
    __shared__ float s_e[KDIM];
    __shared__ float s_bestv;
    __shared__ int   s_besti;

    s_z[tid] = g_znf[(size_t)row * KDIM + tid];
    if (tid == 0) { s_cnt = 0; s_bestv = -3.0f; s_besti = 0x7fffffff; }
    __syncthreads();

    float thr = fdec(g_rowmax[row]) - MARGIN;

    for (int c = tid; c < V; c += 256) {
        if (crow[c] >= thr) {
            int pos = atomicAdd(&s_cnt, 1);
            if (pos < MAXCAND) s_cand[pos] = c;
        }
    }
    __syncthreads();
    int nc = min(s_cnt, MAXCAND);

    for (int i = 0; i < nc; i++) {
        int c = s_cand[i];
        s_e[tid] = g_enf[(size_t)c * KDIM + tid];
        __syncthreads();
        if (tid == 0) {
            float d = 0.f;
            #pragma unroll 8
            for (int k = 0; k < KDIM; k++) d = fmaf(s_z[k], s_e[k], d);
            if (d > s_bestv || (d == s_bestv && c < s_besti)) {
                s_bestv = d; s_besti = c;
            }
        }
        __syncthreads();
    }

    if (tid == 0) out[(size_t)N * (size_t)N + row] = (float)s_besti;
}

// ---------------------------------------------------------------------------
extern "C" void kernel_launch(void* const* d_in, const int* in_sizes, int n_in,
                              void* d_out, int out_size) {
    const float* z = (const float*)d_in[0];
    const float* e = (const float*)d_in[1];
    float* out = (float*)d_out;

    int N = in_sizes[0] / KDIM;   // 8192
    int V = in_sizes[1] / KDIM;   // 4096
    int T = N / TILE;             // 64

    cudaFuncSetAttribute(adj_sym_kernel,
                         cudaFuncAttributeMaxDynamicSharedMemorySize, ADJ_SMEM);

    prep_kernel<<<N + V, 256>>>(z, e, N, V);

    int nTiles = T * (T + 1) / 2; // 2080
    adj_sym_kernel<<<nTiles, 256, ADJ_SMEM>>>(out, N);

    dim3 gCos(V / TILE, N / TILE);
    cos_kernel<<<gCos, 256>>>(N, V);

    rescore_kernel<<<N, 256>>>(out, N, V);
}

// round 11
// speedup vs baseline: 3.8223x; 1.3150x over previous
#include <cuda_runtime.h>
#include <cuda_bf16.h>
#include <cuda_fp16.h>
#include <math.h>

// z [8192,256] f32, embedding [4096,256] f32.
// out = [ sigmoid(z z^T) (8192x8192 f32) , argmax cosine indices (8192 f32) ]
// adj: fp16 asymmetric 2-term (Ah+Al)x(Bh) mma.sync, FMA sigmoid, sym tiles.
// cos: bf16 1-term mma.sync -> bf16 approx matrix + fused row-max.
// rescore: vectorized bf16 gather + exact sequential-fmaf dots (proven R6).
// NOTE: tcgen05 unavailable (harness targets compute_103 without 'a').

#define KDIM 256
#define TILE 128
#define NMAX 8192
#define VMAX 4096
#define AST  40          // smem row stride in elements (80B rows)
#define SST  132         // mirror-staging row stride in f32
#define MARGIN 1.0e-2f   // > bf16-gemm err (3.9e-3) + bf16-store err (2e-3)
#define MAXCAND 256
#define BUFB (TILE * AST * 2)   // 10240 bytes per operand buffer

__device__ __half g_zh [NMAX * KDIM];
__device__ __half g_zl [NMAX * KDIM];
__device__ __nv_bfloat16 g_znh[NMAX * KDIM];
__device__ __nv_bfloat16 g_enh[VMAX * KDIM];
__device__ float g_znf[NMAX * KDIM];
__device__ float g_enf[VMAX * KDIM];
__device__ __nv_bfloat16 g_cosb[(size_t)NMAX * VMAX];
__device__ unsigned g_rowmax[NMAX];   // order-preserving float encoding

// ---------------- order-preserving float <-> uint ---------------------------
__device__ __forceinline__ unsigned fenc(float f) {
    unsigned b = __float_as_uint(f);
    return (b & 0x80000000u) ? ~b : (b | 0x80000000u);
}
__device__ __forceinline__ float fdec(unsigned u) {
    return (u & 0x80000000u) ? __uint_as_float(u & 0x7FFFFFFFu)
                             : __uint_as_float(~u);
}

// ---------------- cp.async helpers ------------------------------------------
#define CP16(sa, gp) \
    asm volatile("cp.async.cg.shared.global [%0], [%1], 16;" \
                 :: "r"(sa), "l"(gp) : "memory")
#define CP_COMMIT() asm volatile("cp.async.commit_group;" ::: "memory")
#define CP_WAIT0()  asm volatile("cp.async.wait_group 0;" ::: "memory")

// ===================== FMA-only sigmoid (no MUFU) ===========================
__device__ __forceinline__ float sigmoid_fast(float x) {
    float ax = fminf(fabsf(x), 30.0f);
    float u  = ax * 1.4426950408889634f;
    float fm = u + 12582912.0f;
    float n  = fm - 12582912.0f;
    float f  = n - u;
    float p  = 1.3333558146428443e-3f;
    p = fmaf(p, f, 9.6181291976353954e-3f);
    p = fmaf(p, f, 5.5504108664798463e-2f);
    p = fmaf(p, f, 2.4022650695910071e-1f);
    p = fmaf(p, f, 6.9314718055994531e-1f);
    p = fmaf(p, f, 1.0f);
    int nbits = (__float_as_int(fm) & 0x7F) << 23;
    float scale = __int_as_float(0x3F800000 - nbits);
    float q = p * scale;
    float d = 1.0f + q;
    float r = fmaf(d, fmaf(d, 0.33333333f, -1.5f), 2.16666667f);
    r = r * (2.0f - d * r);
    r = r * (2.0f - d * r);
    return (x >= 0.0f) ? r : r * q;
}

// ===================== prep: normalize + splits =============================
__global__ void prep_kernel(const float* __restrict__ z,
                            const float* __restrict__ e,
                            int N, int V) {
    int row = blockIdx.x;
    int tid = threadIdx.x;
    bool isZ = row < N;
    const float* src = isZ ? (z + (size_t)row * KDIM)
                           : (e + (size_t)(row - N) * KDIM);
    float v = src[tid];

    float ss = v * v;
    #pragma unroll
    for (int o = 16; o; o >>= 1) ss += __shfl_xor_sync(0xffffffffu, ss, o);
    __shared__ float s_partial[8];
    __shared__ float s_total;
    if ((tid & 31) == 0) s_partial[tid >> 5] = ss;
    __syncthreads();
    if (tid == 0) {
        float t = 0.f;
        #pragma unroll
        for (int i = 0; i < 8; i++) t += s_partial[i];
        s_total = t;
    }
    __syncthreads();
    float inv = 1.0f / fmaxf(sqrtf(s_total), 1e-8f);
    float vn = v * inv;

    if (isZ) {
        size_t o = (size_t)row * KDIM + tid;
        __half h = __float2half_rn(v);
        g_zh[o] = h;
        g_zl[o] = __float2half_rn(v - __half2float(h));
        g_znh[o] = __float2bfloat16(vn);
        g_znf[o] = vn;
        if (tid == 0) g_rowmax[row] = 0u;   // reset per launch
    } else {
        size_t o = (size_t)(row - N) * KDIM + tid;
        g_enh[o] = __float2bfloat16(vn);
        g_enf[o] = vn;
    }
}

// ---------------------------------------------------------------------------
__device__ __forceinline__ void mma_f16(float c[4], const unsigned a[4],
                                        const unsigned b[2]) {
    asm volatile(
        "mma.sync.aligned.m16n8k16.row.col.f32.f16.f16.f32 "
        "{%0,%1,%2,%3}, {%4,%5,%6,%7}, {%8,%9}, {%0,%1,%2,%3};"
        : "+f"(c[0]), "+f"(c[1]), "+f"(c[2]), "+f"(c[3])
        : "r"(a[0]), "r"(a[1]), "r"(a[2]), "r"(a[3]), "r"(b[0]), "r"(b[1]));
}
__device__ __forceinline__ void mma_bf16(float c[4], const unsigned a[4],
                                         const unsigned b[2]) {
    asm volatile(
        "mma.sync.aligned.m16n8k16.row.col.f32.bf16.bf16.f32 "
        "{%0,%1,%2,%3}, {%4,%5,%6,%7}, {%8,%9}, {%0,%1,%2,%3};"
        : "+f"(c[0]), "+f"(c[1]), "+f"(c[2]), "+f"(c[3])
        : "r"(a[0]), "r"(a[1]), "r"(a[2]), "r"(a[3]), "r"(b[0]), "r"(b[1]));
}
#define U32P(base, r, k) (*(const unsigned*)((base) + ((r) * AST + (k)) * 2))

// fp16 2-term chunk: acc += Ah*Bh + Al*Bh
__device__ __forceinline__ void mma_chunk_2t(
    const unsigned char* Ah, const unsigned char* Al, const unsigned char* Bh,
    float acc[4][4][4], int wm, int wn, int g, int t) {
    #pragma unroll
    for (int ks = 0; ks < 2; ks++) {
        int k0 = ks * 16;
        unsigned ah[4][4], al[4][4], bh[4][2];
        #pragma unroll
        for (int ma = 0; ma < 4; ma++) {
            int r0 = wm + ma * 16 + g;
            ah[ma][0] = U32P(Ah, r0,     k0 + 2 * t);
            ah[ma][1] = U32P(Ah, r0 + 8, k0 + 2 * t);
            ah[ma][2] = U32P(Ah, r0,     k0 + 2 * t + 8);
            ah[ma][3] = U32P(Ah, r0 + 8, k0 + 2 * t + 8);
            al[ma][0] = U32P(Al, r0,     k0 + 2 * t);
            al[ma][1] = U32P(Al, r0 + 8, k0 + 2 * t);
            al[ma][2] = U32P(Al, r0,     k0 + 2 * t + 8);
            al[ma][3] = U32P(Al, r0 + 8, k0 + 2 * t + 8);
        }
        #pragma unroll
        for (int nb = 0; nb < 4; nb++) {
            int c0 = wn + nb * 8 + g;
            bh[nb][0] = U32P(Bh, c0, k0 + 2 * t);
            bh[nb][1] = U32P(Bh, c0, k0 + 2 * t + 8);
        }
        #pragma unroll
        for (int ma = 0; ma < 4; ma++)
            #pragma unroll
            for (int nb = 0; nb < 4; nb++) {
                mma_f16(acc[ma][nb], ah[ma], bh[nb]);
                mma_f16(acc[ma][nb], al[ma], bh[nb]);
            }
    }
}

__device__ __forceinline__ void mma_chunk_1t(
    const unsigned char* Ah, const unsigned char* Bh,
    float acc[4][4][4], int wm, int wn, int g, int t) {
    #pragma unroll
    for (int ks = 0; ks < 2; ks++) {
        int k0 = ks * 16;
        unsigned ah[4][4], bh[4][2];
        #pragma unroll
        for (int ma = 0; ma < 4; ma++) {
            int r0 = wm + ma * 16 + g;
            ah[ma][0] = U32P(Ah, r0,     k0 + 2 * t);
            ah[ma][1] = U32P(Ah, r0 + 8, k0 + 2 * t);
            ah[ma][2] = U32P(Ah, r0,     k0 + 2 * t + 8);
            ah[ma][3] = U32P(Ah, r0 + 8, k0 + 2 * t + 8);
        }
        #pragma unroll
        for (int nb = 0; nb < 4; nb++) {
            int c0 = wn + nb * 8 + g;
            bh[nb][0] = U32P(Bh, c0, k0 + 2 * t);
            bh[nb][1] = U32P(Bh, c0, k0 + 2 * t + 8);
        }
        #pragma unroll
        for (int ma = 0; ma < 4; ma++)
            #pragma unroll
            for (int nb = 0; nb < 4; nb++)
                mma_bf16(acc[ma][nb], ah[ma], bh[nb]);
    }
}

// ---------------------------------------------------------------------------
// adj: upper-tri tiles, fp16 2-term, cp.async double buffer, mirror writes.
// ---------------------------------------------------------------------------
#define ADJ_SMEM (2 * 3 * BUFB)

__global__ void __launch_bounds__(256) adj_sym_kernel(float* __restrict__ out, int N) {
    extern __shared__ __align__(16) unsigned char dsm[];
    float (*S)[SST] = (float(*)[SST])dsm;

    const int T = N / TILE;
    int tt = blockIdx.x;
    int bi = 0;
    while (tt >= (T - bi)) { tt -= (T - bi); bi++; }
    int bj = bi + tt;

    int tid = threadIdx.x;
    int warp = tid >> 5, lane = tid & 31;
    int g = lane >> 2, t = lane & 3;
    int wm = (warp >> 2) * 64;
    int wn = (warp & 3) * 32;
    int lrow = tid >> 1;
    int lk = (tid & 1) * 16;

    const __half* srcs[3] = {
        g_zh + (size_t)bi * TILE * KDIM,
        g_zl + (size_t)bi * TILE * KDIM,
        g_zh + (size_t)bj * TILE * KDIM };

    unsigned sm_row = (unsigned)((lrow * AST + lk) * 2);
    unsigned sbase = (unsigned)__cvta_generic_to_shared(dsm);

    {
        size_t goff = (size_t)lrow * KDIM + lk;
        #pragma unroll
        for (int a = 0; a < 3; a++) {
            unsigned sa = sbase + a * BUFB + sm_row;
            CP16(sa,      srcs[a] + goff);
            CP16(sa + 16, srcs[a] + goff + 8);
        }
        CP_COMMIT();
    }

    float acc[4][4][4];
    #pragma unroll
    for (int ma = 0; ma < 4; ma++)
        #pragma unroll
        for (int nb = 0; nb < 4; nb++)
            #pragma unroll
            for (int q = 0; q < 4; q++) acc[ma][nb][q] = 0.f;

    for (int q = 0; q < 8; q++) {
        CP_WAIT0();
        __syncthreads();
        if (q < 7) {
            size_t goff = (size_t)lrow * KDIM + (q + 1) * 32 + lk;
            unsigned boff = ((q + 1) & 1) * 3 * BUFB;
            #pragma unroll
            for (int a = 0; a < 3; a++) {
                unsigned sa = sbase + boff + a * BUFB + sm_row;
                CP16(sa,      srcs[a] + goff);
                CP16(sa + 16, srcs[a] + goff + 8);
            }
            CP_COMMIT();
        }
        const unsigned char* b = dsm + (q & 1) * 3 * BUFB;
        mma_chunk_2t(b, b + BUFB, b + 2 * BUFB, acc, wm, wn, g, t);
    }

    #pragma unroll
    for (int ma = 0; ma < 4; ma++)
        #pragma unroll
        for (int nb = 0; nb < 4; nb++)
            #pragma unroll
            for (int q = 0; q < 4; q++)
                acc[ma][nb][q] = sigmoid_fast(acc[ma][nb][q]);

    #pragma unroll
    for (int ma = 0; ma < 4; ma++) {
        size_t r0 = (size_t)bi * TILE + wm + ma * 16 + g;
        #pragma unroll
        for (int nb = 0; nb < 4; nb++) {
            size_t c = (size_t)bj * TILE + wn + nb * 8 + 2 * t;
            *(float2*)(out + r0 * N + c)       = make_float2(acc[ma][nb][0], acc[ma][nb][1]);
            *(float2*)(out + (r0 + 8) * N + c) = make_float2(acc[ma][nb][2], acc[ma][nb][3]);
        }
    }

    if (bi == bj) return;

    int myHalf = (warp & 3) >> 1;
    #pragma unroll
    for (int ch = 0; ch < 2; ch++) {
        __syncthreads();
        if (myHalf == ch) {
            int cl = (warp & 1) * 32;
            #pragma unroll
            for (int ma = 0; ma < 4; ma++) {
                int r = wm + ma * 16 + g;
                #pragma unroll
                for (int nb = 0; nb < 4; nb++) {
                    int c = cl + nb * 8 + 2 * t;
                    S[c][r]         = acc[ma][nb][0];
                    S[c + 1][r]     = acc[ma][nb][1];
                    S[c][r + 8]     = acc[ma][nb][2];
                    S[c + 1][r + 8] = acc[ma][nb][3];
                }
            }
        }
        __syncthreads();
        #pragma unroll
        for (int q = 0; q < 8; q++) {
            int idx = tid + 256 * q;
            int mr = idx >> 5;
            int fc = idx & 31;
            size_t grow = (size_t)bj * TILE + ch * 64 + mr;
            *(float4*)(out + grow * N + (size_t)bi * TILE + fc * 4) =
                *(const float4*)&S[mr][fc * 4];
        }
    }
}

// ---------------------------------------------------------------------------
// cos: 1-term bf16 GEMM -> bf16 matrix + fused per-row atomic max (on the
// ROUNDED values, so rescore sees a consistent ordering).
// ---------------------------------------------------------------------------
__global__ void __launch_bounds__(256) cos_kernel(int N, int V) {
    __shared__ __align__(16) unsigned char csm[2 * 2 * BUFB];

    int tid = threadIdx.x;
    int warp = tid >> 5, lane = tid & 31;
    int g = lane >> 2, t = lane & 3;
    int wm = (warp >> 2) * 64;
    int wn = (warp & 3) * 32;
    int bi = blockIdx.y;
    int bj = blockIdx.x;
    int lrow = tid >> 1;
    int lk = (tid & 1) * 16;

    const __nv_bfloat16* srcs[2] = {
        g_znh + (size_t)bi * TILE * KDIM, g_enh + (size_t)bj * TILE * KDIM };

    unsigned sm_row = (unsigned)((lrow * AST + lk) * 2);
    unsigned sbase = (unsigned)__cvta_generic_to_shared(csm);

    {
        size_t goff = (size_t)lrow * KDIM + lk;
        #pragma unroll
        for (int a = 0; a < 2; a++) {
            unsigned sa = sbase + a * BUFB + sm_row;
            CP16(sa,      srcs[a] + goff);
            CP16(sa + 16, srcs[a] + goff + 8);
        }
        CP_COMMIT();
    }

    float acc[4][4][4];
    #pragma unroll
    for (int ma = 0; ma < 4; ma++)
        #pragma unroll
        for (int nb = 0; nb < 4; nb++)
            #pragma unroll
            for (int q = 0; q < 4; q++) acc[ma][nb][q] = 0.f;

    for (int q = 0; q < 8; q++) {
        CP_WAIT0();
        __syncthreads();
        if (q < 7) {
            size_t goff = (size_t)lrow * KDIM + (q + 1) * 32 + lk;
            unsigned boff = ((q + 1) & 1) * 2 * BUFB;
            #pragma unroll
            for (int a = 0; a < 2; a++) {
                unsigned sa = sbase + boff + a * BUFB + sm_row;
                CP16(sa,      srcs[a] + goff);
                CP16(sa + 16, srcs[a] + goff + 8);
            }
            CP_COMMIT();
        }
        const unsigned char* b = csm + (q & 1) * 2 * BUFB;
        mma_chunk_1t(b, b + BUFB, acc, wm, wn, g, t);
    }

    #pragma unroll
    for (int ma = 0; ma < 4; ma++) {
        size_t r0 = (size_t)bi * TILE + wm + ma * 16 + g;
        #pragma unroll
        for (int h = 0; h < 2; h++) {
            size_t rr = r0 + h * 8;
            float m = -2.0f;
            #pragma unroll
            for (int nb = 0; nb < 4; nb++) {
                size_t c = (size_t)bj * TILE + wn + nb * 8 + 2 * t;
                unsigned lo = (unsigned)__bfloat16_as_ushort(
                    __float2bfloat16(acc[ma][nb][h * 2 + 0]));
                unsigned hi = (unsigned)__bfloat16_as_ushort(
                    __float2bfloat16(acc[ma][nb][h * 2 + 1]));
                *(unsigned*)(g_cosb + rr * V + c) = lo | (hi << 16);
                m = fmaxf(m, __uint_as_float(lo << 16));
                m = fmaxf(m, __uint_as_float(hi << 16));
            }
            #pragma unroll
            for (int off = 2; off; off >>= 1)
                m = fmaxf(m, __shfl_xor_sync(0xffffffffu, m, off, 4));
            if (t == 0)
                atomicMax(&g_rowmax[rr], fenc(m));
        }
    }
}

// ---------------------------------------------------------------------------
// Rescore: vectorized bf16 gather (threshold from g_rowmax) + exact
// sequential fmaf-chain dots, smallest-index tie-break.
// ---------------------------------------------------------------------------
__global__ void __launch_bounds__(256) rescore_kernel(float* __restrict__ out,
                                                      int N, int V) {
    int row = blockIdx.x;
    int tid = threadIdx.x;
    const uint4* crow = (const uint4*)(g_cosb + (size_t)row * V);  // 8 bf16 each

    __shared__ int   s_cnt;
    __shared__ int   s_cand[MAXCAND];
    __shared__ float s_z[KDIM];
    __shared__ float s_e[KDIM];
    __shared__ float s_bestv;
    __shared__ int   s_besti;

    s_z[tid] = g_znf[(size_t)row * KDIM + tid];
    if (tid == 0) { s_cnt = 0; s_bestv = -3.0f; s_besti = 0x7fffffff; }
    __syncthreads();

    float thr = fdec(g_rowmax[row]) - MARGIN;

    int nvec = V / 8;   // 512
    for (int i = tid; i < nvec; i += 256) {
        uint4 w = crow[i];
        unsigned u[4] = {w.x, w.y, w.z, w.w};
        int cbase = i * 8;
        #pragma unroll
        for (int j = 0; j < 4; j++) {
            float v0 = __uint_as_float(u[j] << 16);
            float v1 = __uint_as_float(u[j] & 0xFFFF0000u);
            if (v0 >= thr) {
                int pos = atomicAdd(&s_cnt, 1);
                if (pos < MAXCAND) s_cand[pos] = cbase + 2 * j;
            }
            if (v1 >= thr) {
                int pos = atomicAdd(&s_cnt, 1);
                if (pos < MAXCAND) s_cand[pos] = cbase + 2 * j + 1;
            }
        }
    }
    __syncthreads();
    int nc = min(s_cnt, MAXCAND);

    for (int i = 0; i < nc; i++) {
        int c = s_cand[i];
        s_e[tid] = g_enf[(size_t)c * KDIM + tid];
        __syncthreads();
        if (tid == 0) {
            float d = 0.f;
            #pragma unroll 8
            for (int k = 0; k < KDIM; k++) d = fmaf(s_z[k], s_e[k], d);
            if (d > s_bestv || (d == s_bestv && c < s_besti)) {
                s_bestv = d; s_besti = c;
            }
        }
        __syncthreads();
    }

    if (tid == 0) out[(size_t)N * (size_t)N + row] = (float)s_besti;
}

// ---------------------------------------------------------------------------
extern "C" void kernel_launch(void* const* d_in, const int* in_sizes, int n_in,
                              void* d_out, int out_size) {
    const float* z = (const float*)d_in[0];
    const float* e = (const float*)d_in[1];
    float* out = (float*)d_out;

    int N = in_sizes[0] / KDIM;   // 8192
    int V = in_sizes[1] / KDIM;   // 4096
    int T = N / TILE;             // 64

    cudaFuncSetAttribute(adj_sym_kernel,
                         cudaFuncAttributeMaxDynamicSharedMemorySize, ADJ_SMEM);

    prep_kernel<<<N + V, 256>>>(z, e, N, V);

    int nTiles = T * (T + 1) / 2; // 2080
    adj_sym_kernel<<<nTiles, 256, ADJ_SMEM>>>(out, N);

    dim3 gCos(V / TILE, N / TILE);
    cos_kernel<<<gCos, 256>>>(N, V);

    rescore_kernel<<<N, 256>>>(out, N, V);
}